// round 2
// baseline (speedup 1.0000x reference)
#include <cuda_runtime.h>
#include <math.h>

#define NB  8
#define NC  256
#define NC2 128
#define NHW 4096

#define BR 128
#define BC 128
#define SP 132   // padded smem row stride (floats)

// Scratch: [3][B][C2][HW] projections and [B][C2][HW] attention output.
__device__ float g_qkv[3ull * NB * NC2 * NHW];
__device__ float g_y[(unsigned long long)NB * NC2 * NHW];

// ---------------------------------------------------------------------------
// Kernel 1: fused theta/phi/g 1x1-conv GEMM.
// grid (NHW/128, 3, NB), block 256. Per CTA: [128 out-ch] x [128 n], K=256.
// ---------------------------------------------------------------------------
__global__ __launch_bounds__(256) void proj_kernel(
    const float* __restrict__ x,
    const float* __restrict__ w_theta, const float* __restrict__ b_theta,
    const float* __restrict__ w_phi,   const float* __restrict__ b_phi,
    const float* __restrict__ w_g,     const float* __restrict__ b_g)
{
    const int bn  = blockIdx.x * 128;
    const int mat = blockIdx.y;
    const int bb  = blockIdx.z;
    const float* w    = (mat == 0) ? w_theta : (mat == 1 ? w_phi : w_g);
    const float* bias = (mat == 0) ? b_theta : (mat == 1 ? b_phi : b_g);
    const float* xb = x + (size_t)bb * NC * NHW;

    __shared__ float As[32][SP];  // [kc][o]
    __shared__ float Bs[32][SP];  // [kc][n]

    const int tid = threadIdx.x;
    const int tyi = tid >> 4, txi = tid & 15;
    const int o0 = tyi * 8, n0 = txi * 8;

    float acc[8][8];
#pragma unroll
    for (int r = 0; r < 8; r++)
#pragma unroll
        for (int j = 0; j < 8; j++) acc[r][j] = 0.f;

    for (int k0 = 0; k0 < NC; k0 += 32) {
#pragma unroll
        for (int it = 0; it < 4; it++) {
            int idx = (tid + it * 256) * 4;      // 0..4095
            int r  = idx >> 5;                   // /32
            int kc = idx & 31;
            float4 v = *(const float4*)(w + r * NC + k0 + kc);
            As[kc + 0][r] = v.x; As[kc + 1][r] = v.y;
            As[kc + 2][r] = v.z; As[kc + 3][r] = v.w;
        }
#pragma unroll
        for (int it = 0; it < 4; it++) {
            int idx = (tid + it * 256) * 4;
            int kc = idx >> 7;                   // /128
            int j  = idx & 127;
            *(float4*)&Bs[kc][j] =
                *(const float4*)(xb + (size_t)(k0 + kc) * NHW + bn + j);
        }
        __syncthreads();
#pragma unroll
        for (int kc = 0; kc < 32; kc++) {
            float a[8], bv[8];
            *(float4*)&a[0]  = *(float4*)&As[kc][o0];
            *(float4*)&a[4]  = *(float4*)&As[kc][o0 + 4];
            *(float4*)&bv[0] = *(float4*)&Bs[kc][n0];
            *(float4*)&bv[4] = *(float4*)&Bs[kc][n0 + 4];
#pragma unroll
            for (int r = 0; r < 8; r++)
#pragma unroll
                for (int j = 0; j < 8; j++)
                    acc[r][j] = fmaf(a[r], bv[j], acc[r][j]);
        }
        __syncthreads();
    }

    float* outp = g_qkv + ((size_t)mat * NB + bb) * NC2 * NHW;
#pragma unroll
    for (int r = 0; r < 8; r++) {
        float bvv = bias[o0 + r];
#pragma unroll
        for (int j = 0; j < 8; j += 4) {
            float4 v;
            v.x = acc[r][j + 0] + bvv; v.y = acc[r][j + 1] + bvv;
            v.z = acc[r][j + 2] + bvv; v.w = acc[r][j + 3] + bvv;
            *(float4*)(outp + (size_t)(o0 + r) * NHW + bn + n0 + j) = v;
        }
    }
}

// ---------------------------------------------------------------------------
// Kernel 2: fused flash-attention. grid (NHW/BR, NB), block 256.
// Q = theta^T (scaled by log2e/sqrt(128) at load), K = phi, V = g.
// Online softmax in log2 domain. Per-thread 8x8 register tiles.
// ---------------------------------------------------------------------------
__global__ __launch_bounds__(256, 1) void attn_kernel()
{
    extern __shared__ float sm[];
    float* Qs = sm;                 // [c][i]  128*SP
    float* KV = sm + 128 * SP;      // [c][j]  128*SP (K then V)
    float* Ps = sm + 2 * 128 * SP;  // [i][j]  128*SP

    const int n0 = blockIdx.x * BR;
    const int bb = blockIdx.y;
    const float* th = g_qkv + ((size_t)0 * NB + bb) * NC2 * NHW;
    const float* ph = g_qkv + ((size_t)1 * NB + bb) * NC2 * NHW;
    const float* gv = g_qkv + ((size_t)2 * NB + bb) * NC2 * NHW;

    const int tid = threadIdx.x;
    const int tyi = tid >> 4, txi = tid & 15;
    const int i0 = tyi * 8;   // query rows owned by this thread
    const int j0 = txi * 8;   // key cols owned in S phase

    const float qs = 1.4426950408889634f * 0.08838834764831845f; // log2e/sqrt(128)

    // Load Q (scaled) once.
#pragma unroll
    for (int it = 0; it < 16; it++) {
        int idx = (tid + it * 256) * 4;
        int c = idx >> 7, i = idx & 127;
        float4 v = *(const float4*)(th + (size_t)c * NHW + n0 + i);
        v.x *= qs; v.y *= qs; v.z *= qs; v.w *= qs;
        *(float4*)&Qs[c * SP + i] = v;
    }

    float m[8], l[8], acc[8][8];
#pragma unroll
    for (int r = 0; r < 8; r++) {
        m[r] = -1e30f; l[r] = 0.f;
#pragma unroll
        for (int cc = 0; cc < 8; cc++) acc[r][cc] = 0.f;
    }

    for (int kb = 0; kb < NHW / BC; kb++) {
        const int m0 = kb * BC;
        __syncthreads();   // previous PV done with KV/Ps (and Qs ready on kb=0... see next sync)
        // Load K tile.
#pragma unroll
        for (int it = 0; it < 16; it++) {
            int idx = (tid + it * 256) * 4;
            int c = idx >> 7, j = idx & 127;
            *(float4*)&KV[c * SP + j] =
                *(const float4*)(ph + (size_t)c * NHW + m0 + j);
        }
        __syncthreads();   // K (and Q) visible

        // S = Q^T K (already in log2 units).
        float s[8][8];
#pragma unroll
        for (int r = 0; r < 8; r++)
#pragma unroll
            for (int j = 0; j < 8; j++) s[r][j] = 0.f;

#pragma unroll 2
        for (int c = 0; c < 128; c++) {
            float qa[8], ka[8];
            *(float4*)&qa[0] = *(float4*)&Qs[c * SP + i0];
            *(float4*)&qa[4] = *(float4*)&Qs[c * SP + i0 + 4];
            *(float4*)&ka[0] = *(float4*)&KV[c * SP + j0];
            *(float4*)&ka[4] = *(float4*)&KV[c * SP + j0 + 4];
#pragma unroll
            for (int r = 0; r < 8; r++)
#pragma unroll
                for (int j = 0; j < 8; j++)
                    s[r][j] = fmaf(qa[r], ka[j], s[r][j]);
        }

        // Online softmax: row stats reduced across the 16 tx lanes (half-warp).
#pragma unroll
        for (int r = 0; r < 8; r++) {
            float mx = s[r][0];
#pragma unroll
            for (int j = 1; j < 8; j++) mx = fmaxf(mx, s[r][j]);
#pragma unroll
            for (int d = 1; d < 16; d <<= 1)
                mx = fmaxf(mx, __shfl_xor_sync(0xffffffffu, mx, d));
            float nm = fmaxf(m[r], mx);
            float e[8];
            float ps = 0.f;
#pragma unroll
            for (int j = 0; j < 8; j++) {
                e[j] = exp2f(s[r][j] - nm);
                ps += e[j];
            }
            *(float4*)&Ps[(i0 + r) * SP + j0]     = make_float4(e[0], e[1], e[2], e[3]);
            *(float4*)&Ps[(i0 + r) * SP + j0 + 4] = make_float4(e[4], e[5], e[6], e[7]);
#pragma unroll
            for (int d = 1; d < 16; d <<= 1)
                ps += __shfl_xor_sync(0xffffffffu, ps, d);
            float alpha = exp2f(m[r] - nm);
            l[r] = l[r] * alpha + ps;
            m[r] = nm;
#pragma unroll
            for (int cc = 0; cc < 8; cc++) acc[r][cc] *= alpha;
        }
        __syncthreads();   // Ps written; KV(K) free

        // Load V tile (overwrites KV).
#pragma unroll
        for (int it = 0; it < 16; it++) {
            int idx = (tid + it * 256) * 4;
            int c = idx >> 7, j = idx & 127;
            *(float4*)&KV[c * SP + j] =
                *(const float4*)(gv + (size_t)c * NHW + m0 + j);
        }
        __syncthreads();   // V and Ps visible

        // O += P * V^T. Thread owns rows i0..i0+7, channels c = txi + 16*cc
        // (stride-16 channel mapping avoids 8*stride ≡ 0 mod 32 bank collapse).
        for (int j = 0; j < BC; j += 4) {
            float p[8][4], v[8][4];
#pragma unroll
            for (int r = 0; r < 8; r++)
                *(float4*)&p[r][0] = *(float4*)&Ps[(i0 + r) * SP + j];
#pragma unroll
            for (int cc = 0; cc < 8; cc++)
                *(float4*)&v[cc][0] = *(float4*)&KV[(txi + 16 * cc) * SP + j];
#pragma unroll
            for (int r = 0; r < 8; r++)
#pragma unroll
                for (int cc = 0; cc < 8; cc++) {
                    acc[r][cc] = fmaf(p[r][0], v[cc][0], acc[r][cc]);
                    acc[r][cc] = fmaf(p[r][1], v[cc][1], acc[r][cc]);
                    acc[r][cc] = fmaf(p[r][2], v[cc][2], acc[r][cc]);
                    acc[r][cc] = fmaf(p[r][3], v[cc][3], acc[r][cc]);
                }
        }
    }

    // Epilogue: y[b][c][n] = O[n][c] / l[n]
    float* yb = g_y + (size_t)bb * NC2 * NHW;
#pragma unroll
    for (int r = 0; r < 8; r++) {
        float inv = 1.0f / l[r];
#pragma unroll
        for (int cc = 0; cc < 8; cc++)
            yb[(size_t)(txi + 16 * cc) * NHW + n0 + i0 + r] = acc[r][cc] * inv;
    }
}

// ---------------------------------------------------------------------------
// Kernel 3: out 1x1 conv + BatchNorm(eval) + residual.
// grid (NHW/128, NC/128, NB), block 256. K = 128.
// ---------------------------------------------------------------------------
__global__ __launch_bounds__(256) void out_kernel(
    const float* __restrict__ x,
    const float* __restrict__ w_out, const float* __restrict__ b_out,
    const float* __restrict__ gamma, const float* __restrict__ beta,
    const float* __restrict__ rmean, const float* __restrict__ rvar,
    float* __restrict__ out)
{
    const int bn  = blockIdx.x * 128;
    const int oc0 = blockIdx.y * 128;
    const int bb  = blockIdx.z;
    const float* yb = g_y + (size_t)bb * NC2 * NHW;

    __shared__ float As[32][SP];
    __shared__ float Bs[32][SP];

    const int tid = threadIdx.x;
    const int tyi = tid >> 4, txi = tid & 15;
    const int o0 = tyi * 8, n0 = txi * 8;

    float acc[8][8];
#pragma unroll
    for (int r = 0; r < 8; r++)
#pragma unroll
        for (int j = 0; j < 8; j++) acc[r][j] = 0.f;

    for (int k0 = 0; k0 < NC2; k0 += 32) {
#pragma unroll
        for (int it = 0; it < 4; it++) {
            int idx = (tid + it * 256) * 4;
            int r  = idx >> 5;
            int kc = idx & 31;
            float4 v = *(const float4*)(w_out + (oc0 + r) * NC2 + k0 + kc);
            As[kc + 0][r] = v.x; As[kc + 1][r] = v.y;
            As[kc + 2][r] = v.z; As[kc + 3][r] = v.w;
        }
#pragma unroll
        for (int it = 0; it < 4; it++) {
            int idx = (tid + it * 256) * 4;
            int kc = idx >> 7;
            int j  = idx & 127;
            *(float4*)&Bs[kc][j] =
                *(const float4*)(yb + (size_t)(k0 + kc) * NHW + bn + j);
        }
        __syncthreads();
#pragma unroll
        for (int kc = 0; kc < 32; kc++) {
            float a[8], bv[8];
            *(float4*)&a[0]  = *(float4*)&As[kc][o0];
            *(float4*)&a[4]  = *(float4*)&As[kc][o0 + 4];
            *(float4*)&bv[0] = *(float4*)&Bs[kc][n0];
            *(float4*)&bv[4] = *(float4*)&Bs[kc][n0 + 4];
#pragma unroll
            for (int r = 0; r < 8; r++)
#pragma unroll
                for (int j = 0; j < 8; j++)
                    acc[r][j] = fmaf(a[r], bv[j], acc[r][j]);
        }
        __syncthreads();
    }

    const float* xb = x + (size_t)bb * NC * NHW;
    float* ob = out + (size_t)bb * NC * NHW;
#pragma unroll
    for (int r = 0; r < 8; r++) {
        const int o = oc0 + o0 + r;
        float inv = gamma[o] / sqrtf(rvar[o] + 1e-5f);
        float sh  = beta[o] - rmean[o] * inv;
        float bo  = b_out[o];
#pragma unroll
        for (int j = 0; j < 8; j += 4) {
            float4 xv = *(const float4*)(xb + (size_t)o * NHW + bn + n0 + j);
            float4 v;
            v.x = xv.x + (acc[r][j + 0] + bo) * inv + sh;
            v.y = xv.y + (acc[r][j + 1] + bo) * inv + sh;
            v.z = xv.z + (acc[r][j + 2] + bo) * inv + sh;
            v.w = xv.w + (acc[r][j + 3] + bo) * inv + sh;
            *(float4*)(ob + (size_t)o * NHW + bn + n0 + j) = v;
        }
    }
}

// ---------------------------------------------------------------------------
extern "C" void kernel_launch(void* const* d_in, const int* in_sizes, int n_in,
                              void* d_out, int out_size)
{
    const float* x       = (const float*)d_in[0];
    const float* w_theta = (const float*)d_in[1];
    const float* b_theta = (const float*)d_in[2];
    const float* w_phi   = (const float*)d_in[3];
    const float* b_phi   = (const float*)d_in[4];
    const float* w_g     = (const float*)d_in[5];
    const float* b_g     = (const float*)d_in[6];
    const float* w_out   = (const float*)d_in[7];
    const float* b_out   = (const float*)d_in[8];
    const float* gamma   = (const float*)d_in[9];
    const float* beta    = (const float*)d_in[10];
    const float* rmean   = (const float*)d_in[11];
    const float* rvar    = (const float*)d_in[12];
    float* out = (float*)d_out;

    const int attn_smem = 3 * 128 * SP * 4;   // 202752 B
    cudaFuncSetAttribute(attn_kernel,
                         cudaFuncAttributeMaxDynamicSharedMemorySize, attn_smem);

    dim3 g1(NHW / 128, 3, NB);
    proj_kernel<<<g1, 256>>>(x, w_theta, b_theta, w_phi, b_phi, w_g, b_g);

    dim3 g2(NHW / BR, NB);
    attn_kernel<<<g2, 256, attn_smem>>>();

    dim3 g3(NHW / 128, NC / 128, NB);
    out_kernel<<<g3, 256>>>(x, w_out, b_out, gamma, beta, rmean, rvar, out);
}

// round 4
// speedup vs baseline: 4.1540x; 4.1540x over previous
#include <cuda_runtime.h>
#include <cuda_bf16.h>
#include <math.h>
#include <stdint.h>

#define NB  8
#define NC  256
#define NC2 128
#define NHW 4096
#define SP  132

// ---------------------------------------------------------------------------
// Scratch (device globals; no allocation allowed)
// ---------------------------------------------------------------------------
__device__ float g_y[(size_t)NB * NC2 * NHW];          // attn out [b][c][n] fp32
__device__ __nv_bfloat16 g_Q[(size_t)NB * NHW * NC2];  // [b][n][c], pre-scaled
__device__ __nv_bfloat16 g_K[(size_t)NB * NHW * NC2];  // [b][n][c]
__device__ __nv_bfloat16 g_V[(size_t)NB * NC2 * NHW];  // [b][c][n]

// ---------------------------------------------------------------------------
// Helpers
// ---------------------------------------------------------------------------
__device__ __forceinline__ uint32_t smem_u32(const void* p) {
    uint32_t a;
    asm("{ .reg .u64 t; cvta.to.shared.u64 t, %1; cvt.u32.u64 %0, t; }" : "=r"(a) : "l"(p));
    return a;
}
__device__ __forceinline__ void cp_async16(uint32_t dst, const void* src) {
    asm volatile("cp.async.cg.shared.global [%0], [%1], 16;" :: "r"(dst), "l"(src) : "memory");
}
#define CP_COMMIT() asm volatile("cp.async.commit_group;" ::: "memory")
#define CP_WAIT1()  asm volatile("cp.async.wait_group 1;" ::: "memory")
#define CP_WAIT0()  asm volatile("cp.async.wait_group 0;" ::: "memory")

__device__ __forceinline__ void ldmx4(uint32_t addr, uint32_t& r0, uint32_t& r1,
                                      uint32_t& r2, uint32_t& r3) {
    asm volatile("ldmatrix.sync.aligned.m8n8.x4.shared.b16 {%0,%1,%2,%3}, [%4];"
                 : "=r"(r0), "=r"(r1), "=r"(r2), "=r"(r3) : "r"(addr));
}
__device__ __forceinline__ void mma16816(float* c, const uint32_t* a,
                                         uint32_t b0, uint32_t b1) {
    asm volatile(
        "mma.sync.aligned.m16n8k16.row.col.f32.bf16.bf16.f32 "
        "{%0,%1,%2,%3}, {%4,%5,%6,%7}, {%8,%9}, {%0,%1,%2,%3};"
        : "+f"(c[0]), "+f"(c[1]), "+f"(c[2]), "+f"(c[3])
        : "r"(a[0]), "r"(a[1]), "r"(a[2]), "r"(a[3]), "r"(b0), "r"(b1));
}
__device__ __forceinline__ float fast_exp2(float x) {
    float r; asm("ex2.approx.f32 %0, %1;" : "=f"(r) : "f"(x)); return r;
}
__device__ __forceinline__ uint32_t packbf(float a, float b) {
    __nv_bfloat162 t = __floats2bfloat162_rn(a, b);
    return *(uint32_t*)&t;
}

// log2(e) / sqrt(128)
#define QSCALE 0.12751491563218832f

// ---------------------------------------------------------------------------
// Kernel 1: fused theta/phi/g 1x1-conv GEMM (fp32 compute, bf16 output).
// mat 0 -> g_Q [n][c] scaled; mat 1 -> g_K [n][c]; mat 2 -> g_V [c][n].
// ---------------------------------------------------------------------------
__global__ __launch_bounds__(256) void proj_kernel(
    const float* __restrict__ x,
    const float* __restrict__ w_theta, const float* __restrict__ b_theta,
    const float* __restrict__ w_phi,   const float* __restrict__ b_phi,
    const float* __restrict__ w_g,     const float* __restrict__ b_g)
{
    const int bn  = blockIdx.x * 128;
    const int mat = blockIdx.y;
    const int bb  = blockIdx.z;
    const float* w    = (mat == 0) ? w_theta : (mat == 1 ? w_phi : w_g);
    const float* bias = (mat == 0) ? b_theta : (mat == 1 ? b_phi : b_g);
    const float* xb = x + (size_t)bb * NC * NHW;

    __shared__ float As[32][SP];
    __shared__ float Bs[32][SP];

    const int tid = threadIdx.x;
    const int tyi = tid >> 4, txi = tid & 15;
    const int o0 = tyi * 8, n0 = txi * 8;

    float acc[8][8];
#pragma unroll
    for (int r = 0; r < 8; r++)
#pragma unroll
        for (int j = 0; j < 8; j++) acc[r][j] = 0.f;

    for (int k0 = 0; k0 < NC; k0 += 32) {
#pragma unroll
        for (int it = 0; it < 4; it++) {
            int idx = (tid + it * 256) * 4;
            int r  = idx >> 5;
            int kc = idx & 31;
            float4 v = *(const float4*)(w + r * NC + k0 + kc);
            As[kc + 0][r] = v.x; As[kc + 1][r] = v.y;
            As[kc + 2][r] = v.z; As[kc + 3][r] = v.w;
        }
#pragma unroll
        for (int it = 0; it < 4; it++) {
            int idx = (tid + it * 256) * 4;
            int kc = idx >> 7;
            int j  = idx & 127;
            *(float4*)&Bs[kc][j] =
                *(const float4*)(xb + (size_t)(k0 + kc) * NHW + bn + j);
        }
        __syncthreads();
#pragma unroll
        for (int kc = 0; kc < 32; kc++) {
            float a[8], bv[8];
            *(float4*)&a[0]  = *(float4*)&As[kc][o0];
            *(float4*)&a[4]  = *(float4*)&As[kc][o0 + 4];
            *(float4*)&bv[0] = *(float4*)&Bs[kc][n0];
            *(float4*)&bv[4] = *(float4*)&Bs[kc][n0 + 4];
#pragma unroll
            for (int r = 0; r < 8; r++)
#pragma unroll
                for (int j = 0; j < 8; j++)
                    acc[r][j] = fmaf(a[r], bv[j], acc[r][j]);
        }
        __syncthreads();
    }

    if (mat < 2) {
        __nv_bfloat16* dst = (mat == 0 ? g_Q : g_K) + (size_t)bb * NHW * NC2;
        const float sc = (mat == 0) ? QSCALE : 1.0f;
#pragma unroll
        for (int j = 0; j < 8; j++) {
            uint32_t pk[4];
#pragma unroll
            for (int h = 0; h < 4; h++)
                pk[h] = packbf((acc[2 * h][j]     + bias[o0 + 2 * h])     * sc,
                               (acc[2 * h + 1][j] + bias[o0 + 2 * h + 1]) * sc);
            *(uint4*)(dst + (size_t)(bn + n0 + j) * NC2 + o0) =
                make_uint4(pk[0], pk[1], pk[2], pk[3]);
        }
    } else {
        __nv_bfloat16* dst = g_V + (size_t)bb * NC2 * NHW;
#pragma unroll
        for (int r = 0; r < 8; r++) {
            float bvv = bias[o0 + r];
            uint32_t pk[4];
#pragma unroll
            for (int h = 0; h < 4; h++)
                pk[h] = packbf(acc[r][2 * h] + bvv, acc[r][2 * h + 1] + bvv);
            *(uint4*)(dst + (size_t)(o0 + r) * NHW + bn + n0) =
                make_uint4(pk[0], pk[1], pk[2], pk[3]);
        }
    }
}

// ---------------------------------------------------------------------------
// Kernel 2: bf16 mma.sync flash attention (no running max; fp32 row-sum).
// grid (64, 8), 128 threads (4 warps x 16 query rows). BC=64 keys per tile.
// smem: Q[64x136] | K0[64x136] | K1 | V0[128x72] | V1   (bf16, padded rows)
// Epilogue stages O through smem for coalesced stores.
// ---------------------------------------------------------------------------
#define KROW 136            // Q/K row stride in bf16 elems (272 B)
#define VROW 72             // V row stride in bf16 elems (144 B)
#define QBYTES  (64 * KROW * 2)    // 17408
#define KBYTES  (64 * KROW * 2)    // 17408
#define VBYTES  (128 * VROW * 2)   // 18432
#define ATTN_SMEM (QBYTES + 2 * KBYTES + 2 * VBYTES)   // 89088

__global__ __launch_bounds__(128, 2) void attn_kernel()
{
    extern __shared__ char dsm[];
    const uint32_t base = smem_u32(dsm);
    const uint32_t qsm = base;
    const uint32_t ksm[2] = { base + QBYTES, base + QBYTES + KBYTES };
    const uint32_t vsm[2] = { base + QBYTES + 2 * KBYTES,
                              base + QBYTES + 2 * KBYTES + VBYTES };

    const int tid  = threadIdx.x;
    const int warp = tid >> 5, lane = tid & 31;
    const int n0 = blockIdx.x * 64;
    const int bb = blockIdx.y;
    const __nv_bfloat16* Qg = g_Q + (size_t)bb * NHW * NC2;
    const __nv_bfloat16* Kg = g_K + (size_t)bb * NHW * NC2;
    const __nv_bfloat16* Vg = g_V + (size_t)bb * NC2 * NHW;

    // ---- async tile loaders (all 128 threads) ----
    // Q/K tile: 64 rows x 128 c ; V tile: 128 rows(c) x 64 keys
    const int qk_row = tid >> 4;          // base row, 8 chunks/thread
    const int qk_co  = (tid & 15) * 8;    // elem offset
    const int v_row  = tid >> 3;
    const int v_co   = (tid & 7) * 8;

#define LOAD_QK(dstbase, srcbase) do {                                        \
    const __nv_bfloat16* _s = (srcbase) + (size_t)qk_row * NC2 + qk_co;       \
    uint32_t _d = (dstbase) + qk_row * (KROW * 2) + qk_co * 2;                \
    _Pragma("unroll")                                                         \
    for (int p = 0; p < 8; p++)                                               \
        cp_async16(_d + p * 8 * (KROW * 2), _s + (size_t)p * 8 * NC2);        \
} while (0)

#define LOAD_V(dstbase, m0) do {                                              \
    const __nv_bfloat16* _s = Vg + (size_t)v_row * NHW + (m0) + v_co;         \
    uint32_t _d = (dstbase) + v_row * (VROW * 2) + v_co * 2;                  \
    _Pragma("unroll")                                                         \
    for (int p = 0; p < 8; p++)                                               \
        cp_async16(_d + p * 16 * (VROW * 2), _s + (size_t)p * 16 * NHW);      \
} while (0)

    // Prologue: Q + tile0, then tile1.
    LOAD_QK(qsm, Qg + (size_t)n0 * NC2);
    LOAD_QK(ksm[0], Kg);
    LOAD_V(vsm[0], 0);
    CP_COMMIT();
    LOAD_QK(ksm[1], Kg + (size_t)64 * NC2);
    LOAD_V(vsm[1], 64);
    CP_COMMIT();

    // ldmatrix per-thread address components
    const int g   = lane >> 3;       // tile group 0..3
    const int row = lane & 7;
    // Q/K frag addr: row = (g&1 -> +8) + row, col-half = (g>>1)*8 ... for Q
    const uint32_t qbase = qsm + (warp * 16 + (g & 1) * 8 + row) * (KROW * 2)
                               + ((g >> 1) * 8) * 2;
    // K frag: n = (g>>1)*8 + row ; k-half = (g&1)*8
    const uint32_t kfoff = ((g >> 1) * 8 + row) * (KROW * 2) + ((g & 1) * 8) * 2;
    // V frag: c = (g>>1)*8 + row ; key-half = (g&1)*8
    const uint32_t vfoff = ((g >> 1) * 8 + row) * (VROW * 2) + ((g & 1) * 8) * 2;

    uint32_t qf[8][4];       // Q fragments, resident all loop
    float o[16][4];          // O accumulator (16 c-tiles x 4)
    float lsum0 = 0.f, lsum1 = 0.f;
#pragma unroll
    for (int i = 0; i < 16; i++)
#pragma unroll
        for (int j = 0; j < 4; j++) o[i][j] = 0.f;

    for (int kt = 0; kt < 64; kt++) {
        CP_WAIT1();
        __syncthreads();
        if (kt == 0) {
#pragma unroll
            for (int ks = 0; ks < 8; ks++)
                ldmx4(qbase + ks * 32, qf[ks][0], qf[ks][1], qf[ks][2], qf[ks][3]);
        }
        const uint32_t kb = ksm[kt & 1] + kfoff;
        const uint32_t vb = vsm[kt & 1] + vfoff;

        // S = Q K^T (16 x 64 per warp)
        float s[8][4];
#pragma unroll
        for (int i = 0; i < 8; i++)
#pragma unroll
            for (int j = 0; j < 4; j++) s[i][j] = 0.f;
#pragma unroll
        for (int ks = 0; ks < 8; ks++) {
#pragma unroll
            for (int nt2 = 0; nt2 < 4; nt2++) {
                uint32_t b0, b1, b2, b3;
                ldmx4(kb + nt2 * 16 * (KROW * 2) + ks * 32, b0, b1, b2, b3);
                mma16816(s[2 * nt2],     qf[ks], b0, b1);
                mma16816(s[2 * nt2 + 1], qf[ks], b2, b3);
            }
        }

        // softmax (no max): e = exp2(s); row sums; repack as A-fragments
        uint32_t a[4][4];
#pragma unroll
        for (int nt = 0; nt < 8; nt++) {
            float e0 = fast_exp2(s[nt][0]);
            float e1 = fast_exp2(s[nt][1]);
            float e2 = fast_exp2(s[nt][2]);
            float e3 = fast_exp2(s[nt][3]);
            lsum0 += e0 + e1;
            lsum1 += e2 + e3;
            a[nt >> 1][(nt & 1) * 2]     = packbf(e0, e1);
            a[nt >> 1][(nt & 1) * 2 + 1] = packbf(e2, e3);
        }

        // O += P V^T
#pragma unroll
        for (int ks = 0; ks < 4; ks++) {
#pragma unroll
            for (int ct2 = 0; ct2 < 8; ct2++) {
                uint32_t b0, b1, b2, b3;
                ldmx4(vb + ct2 * 16 * (VROW * 2) + ks * 32, b0, b1, b2, b3);
                mma16816(o[2 * ct2],     a[ks], b0, b1);
                mma16816(o[2 * ct2 + 1], a[ks], b2, b3);
            }
        }

        __syncthreads();   // done reading buffer kt&1 before overwrite
        if (kt + 2 < 64) {
            LOAD_QK(ksm[kt & 1], Kg + (size_t)(kt + 2) * 64 * NC2);
            LOAD_V(vsm[kt & 1], (kt + 2) * 64);
        }
        CP_COMMIT();       // always exactly one group per iteration
    }

    // ---- epilogue ----
    CP_WAIT0();
    __syncthreads();

    // final row-sum reduce across the 4 lanes sharing each row (lane^1, lane^2)
    lsum0 += __shfl_xor_sync(0xffffffffu, lsum0, 1);
    lsum0 += __shfl_xor_sync(0xffffffffu, lsum0, 2);
    lsum1 += __shfl_xor_sync(0xffffffffu, lsum1, 1);
    lsum1 += __shfl_xor_sync(0xffffffffu, lsum1, 2);
    const float inv0 = 1.0f / lsum0;
    const float inv1 = 1.0f / lsum1;

    // stage O into smem [c:128][q:64+4 pad] fp32 (reuses tile smem: 34816 B)
    float* es = (float*)dsm;
    const int m_lo = warp * 16 + (lane >> 2);
#pragma unroll
    for (int nt = 0; nt < 16; nt++) {
        int c = nt * 8 + (lane & 3) * 2;
        es[(c)     * 68 + m_lo]     = o[nt][0] * inv0;
        es[(c + 1) * 68 + m_lo]     = o[nt][1] * inv0;
        es[(c)     * 68 + m_lo + 8] = o[nt][2] * inv1;
        es[(c + 1) * 68 + m_lo + 8] = o[nt][3] * inv1;
    }
    __syncthreads();

    float* yb = g_y + (size_t)bb * NC2 * NHW;
#pragma unroll
    for (int p = 0; p < 16; p++) {
        int id = tid + p * 128;           // 2048 chunks of 4 floats
        int c  = id >> 4;
        int co = (id & 15) * 4;
        *(float4*)(yb + (size_t)c * NHW + n0 + co) = *(float4*)(es + c * 68 + co);
    }
}

// ---------------------------------------------------------------------------
// Kernel 3: out 1x1 conv + BN(eval) + residual (fp32 SIMT).
// ---------------------------------------------------------------------------
__global__ __launch_bounds__(256) void out_kernel(
    const float* __restrict__ x,
    const float* __restrict__ w_out, const float* __restrict__ b_out,
    const float* __restrict__ gamma, const float* __restrict__ beta,
    const float* __restrict__ rmean, const float* __restrict__ rvar,
    float* __restrict__ out)
{
    const int bn  = blockIdx.x * 128;
    const int oc0 = blockIdx.y * 128;
    const int bb  = blockIdx.z;
    const float* yb = g_y + (size_t)bb * NC2 * NHW;

    __shared__ float As[32][SP];
    __shared__ float Bs[32][SP];

    const int tid = threadIdx.x;
    const int tyi = tid >> 4, txi = tid & 15;
    const int o0 = tyi * 8, n0 = txi * 8;

    float acc[8][8];
#pragma unroll
    for (int r = 0; r < 8; r++)
#pragma unroll
        for (int j = 0; j < 8; j++) acc[r][j] = 0.f;

    for (int k0 = 0; k0 < NC2; k0 += 32) {
#pragma unroll
        for (int it = 0; it < 4; it++) {
            int idx = (tid + it * 256) * 4;
            int r  = idx >> 5;
            int kc = idx & 31;
            float4 v = *(const float4*)(w_out + (oc0 + r) * NC2 + k0 + kc);
            As[kc + 0][r] = v.x; As[kc + 1][r] = v.y;
            As[kc + 2][r] = v.z; As[kc + 3][r] = v.w;
        }
#pragma unroll
        for (int it = 0; it < 4; it++) {
            int idx = (tid + it * 256) * 4;
            int kc = idx >> 7;
            int j  = idx & 127;
            *(float4*)&Bs[kc][j] =
                *(const float4*)(yb + (size_t)(k0 + kc) * NHW + bn + j);
        }
        __syncthreads();
#pragma unroll
        for (int kc = 0; kc < 32; kc++) {
            float a[8], bv[8];
            *(float4*)&a[0]  = *(float4*)&As[kc][o0];
            *(float4*)&a[4]  = *(float4*)&As[kc][o0 + 4];
            *(float4*)&bv[0] = *(float4*)&Bs[kc][n0];
            *(float4*)&bv[4] = *(float4*)&Bs[kc][n0 + 4];
#pragma unroll
            for (int r = 0; r < 8; r++)
#pragma unroll
                for (int j = 0; j < 8; j++)
                    acc[r][j] = fmaf(a[r], bv[j], acc[r][j]);
        }
        __syncthreads();
    }

    const float* xb = x + (size_t)bb * NC * NHW;
    float* ob = out + (size_t)bb * NC * NHW;
#pragma unroll
    for (int r = 0; r < 8; r++) {
        const int o = oc0 + o0 + r;
        float inv = gamma[o] / sqrtf(rvar[o] + 1e-5f);
        float sh  = beta[o] - rmean[o] * inv;
        float bo  = b_out[o];
#pragma unroll
        for (int j = 0; j < 8; j += 4) {
            float4 xv = *(const float4*)(xb + (size_t)o * NHW + bn + n0 + j);
            float4 v;
            v.x = xv.x + (acc[r][j + 0] + bo) * inv + sh;
            v.y = xv.y + (acc[r][j + 1] + bo) * inv + sh;
            v.z = xv.z + (acc[r][j + 2] + bo) * inv + sh;
            v.w = xv.w + (acc[r][j + 3] + bo) * inv + sh;
            *(float4*)(ob + (size_t)o * NHW + bn + n0 + j) = v;
        }
    }
}

// ---------------------------------------------------------------------------
extern "C" void kernel_launch(void* const* d_in, const int* in_sizes, int n_in,
                              void* d_out, int out_size)
{
    const float* x       = (const float*)d_in[0];
    const float* w_theta = (const float*)d_in[1];
    const float* b_theta = (const float*)d_in[2];
    const float* w_phi   = (const float*)d_in[3];
    const float* b_phi   = (const float*)d_in[4];
    const float* w_g     = (const float*)d_in[5];
    const float* b_g     = (const float*)d_in[6];
    const float* w_out   = (const float*)d_in[7];
    const float* b_out   = (const float*)d_in[8];
    const float* gamma   = (const float*)d_in[9];
    const float* beta    = (const float*)d_in[10];
    const float* rmean   = (const float*)d_in[11];
    const float* rvar    = (const float*)d_in[12];
    float* out = (float*)d_out;

    cudaFuncSetAttribute(attn_kernel,
                         cudaFuncAttributeMaxDynamicSharedMemorySize, ATTN_SMEM);

    dim3 g1(NHW / 128, 3, NB);
    proj_kernel<<<g1, 256>>>(x, w_theta, b_theta, w_phi, b_phi, w_g, b_g);

    dim3 g2(NHW / 64, NB);
    attn_kernel<<<g2, 128, ATTN_SMEM>>>();

    dim3 g3(NHW / 128, NC / 128, NB);
    out_kernel<<<g3, 256>>>(x, w_out, b_out, gamma, beta, rmean, rvar, out);
}

// round 5
// speedup vs baseline: 5.8778x; 1.4150x over previous
#include <cuda_runtime.h>
#include <cuda_bf16.h>
#include <math.h>
#include <stdint.h>

#define NB  8
#define NC  256
#define NC2 128
#define NHW 4096

// ---------------------------------------------------------------------------
// Scratch (device globals; no allocation allowed)
// ---------------------------------------------------------------------------
__device__ __nv_bfloat16 g_X[(size_t)NB * NHW * NC];    // x transposed [b][n][c]
__device__ __nv_bfloat16 g_Q[(size_t)NB * NHW * NC2];   // [b][n][c], pre-scaled
__device__ __nv_bfloat16 g_K[(size_t)NB * NHW * NC2];   // [b][n][c]
__device__ __nv_bfloat16 g_V[(size_t)NB * NC2 * NHW];   // [b][c][n]
__device__ __nv_bfloat16 g_Yb[(size_t)NB * NHW * NC2];  // attn out [b][n][c]

// ---------------------------------------------------------------------------
// Helpers
// ---------------------------------------------------------------------------
__device__ __forceinline__ uint32_t smem_u32(const void* p) {
    uint32_t a;
    asm("{ .reg .u64 t; cvta.to.shared.u64 t, %1; cvt.u32.u64 %0, t; }" : "=r"(a) : "l"(p));
    return a;
}
__device__ __forceinline__ void cp_async16(uint32_t dst, const void* src) {
    asm volatile("cp.async.cg.shared.global [%0], [%1], 16;" :: "r"(dst), "l"(src) : "memory");
}
#define CP_COMMIT() asm volatile("cp.async.commit_group;" ::: "memory")
#define CP_WAIT1()  asm volatile("cp.async.wait_group 1;" ::: "memory")
#define CP_WAIT0()  asm volatile("cp.async.wait_group 0;" ::: "memory")

__device__ __forceinline__ void ldmx4(uint32_t addr, uint32_t& r0, uint32_t& r1,
                                      uint32_t& r2, uint32_t& r3) {
    asm volatile("ldmatrix.sync.aligned.m8n8.x4.shared.b16 {%0,%1,%2,%3}, [%4];"
                 : "=r"(r0), "=r"(r1), "=r"(r2), "=r"(r3) : "r"(addr));
}
__device__ __forceinline__ void mma16816(float* c, const uint32_t* a,
                                         uint32_t b0, uint32_t b1) {
    asm volatile(
        "mma.sync.aligned.m16n8k16.row.col.f32.bf16.bf16.f32 "
        "{%0,%1,%2,%3}, {%4,%5,%6,%7}, {%8,%9}, {%0,%1,%2,%3};"
        : "+f"(c[0]), "+f"(c[1]), "+f"(c[2]), "+f"(c[3])
        : "r"(a[0]), "r"(a[1]), "r"(a[2]), "r"(a[3]), "r"(b0), "r"(b1));
}
__device__ __forceinline__ float fast_exp2(float x) {
    float r; asm("ex2.approx.f32 %0, %1;" : "=f"(r) : "f"(x)); return r;
}
__device__ __forceinline__ uint32_t packbf(float a, float b) {
    __nv_bfloat162 t = __floats2bfloat162_rn(a, b);
    return *(uint32_t*)&t;
}

// log2(e) / sqrt(128)
#define QSCALE 0.12751491563218832f

// ---------------------------------------------------------------------------
// Kernel 0: x [b][c][n] fp32 -> g_X [b][n][c] bf16. grid (64, 4, 8), 128 thr.
// ---------------------------------------------------------------------------
__global__ __launch_bounds__(128) void convert_kernel(const float* __restrict__ x)
{
    __shared__ float sm[64][68];
    const int n0 = blockIdx.x * 64;
    const int c0 = blockIdx.y * 64;
    const int bb = blockIdx.z;
    const int tid = threadIdx.x;
    const float* xb = x + (size_t)bb * NC * NHW;

#pragma unroll
    for (int p = 0; p < 8; p++) {
        int id = tid + p * 128;           // 1024 float4 chunks
        int row = id >> 4;                // c within tile
        int q = id & 15;                  // n chunk
        *(float4*)&sm[row][q * 4] =
            *(const float4*)(xb + (size_t)(c0 + row) * NHW + n0 + q * 4);
    }
    __syncthreads();

    __nv_bfloat16* dst = g_X + (size_t)bb * NHW * NC;
#pragma unroll
    for (int p = 0; p < 4; p++) {
        int id = tid + p * 128;           // 512 uint4 chunks
        int n = id >> 3;
        int q = id & 7;
        uint32_t pk[4];
#pragma unroll
        for (int h = 0; h < 4; h++)
            pk[h] = packbf(sm[q * 8 + 2 * h][n], sm[q * 8 + 2 * h + 1][n]);
        *(uint4*)(dst + (size_t)(n0 + n) * NC + c0 + q * 8) =
            make_uint4(pk[0], pk[1], pk[2], pk[3]);
    }
}

// ---------------------------------------------------------------------------
// Kernel 1: proj GEMM (bf16 mma). grid (32, 3, 8), 256 thr (8 warps 4x2).
// C[o 128][n 128] = sum_c W[o][c] * X[n][c], K=256 smem resident.
// mat 0 -> g_Q [n][c] scaled; 1 -> g_K [n][c]; 2 -> g_V [c][n].
// smem: Ws bf16[128][264] | Xs bf16[128][264]; epilogue reuses Ws as fp32[128][132].
// ---------------------------------------------------------------------------
#define PRW 264
#define PROJ_SMEM (2 * 128 * PRW * 2)   // 135168

__global__ __launch_bounds__(256) void proj_mma(
    const float* __restrict__ w_theta, const float* __restrict__ b_theta,
    const float* __restrict__ w_phi,   const float* __restrict__ b_phi,
    const float* __restrict__ w_g,     const float* __restrict__ b_g)
{
    extern __shared__ char dsm[];
    const uint32_t ws = smem_u32(dsm);
    const uint32_t xs = ws + 128 * PRW * 2;

    const int n0  = blockIdx.x * 128;
    const int mat = blockIdx.y;
    const int bb  = blockIdx.z;
    const float* w    = (mat == 0) ? w_theta : (mat == 1 ? w_phi : w_g);
    const float* bias = (mat == 0) ? b_theta : (mat == 1 ? b_phi : b_g);

    const int tid  = threadIdx.x;
    const int warp = tid >> 5, lane = tid & 31;
    const int wm = warp & 3, wn = warp >> 2;

    // Load X tile via cp.async: [128 n][256 c] bf16
    {
        const __nv_bfloat16* src = g_X + (size_t)bb * NHW * NC + (size_t)n0 * NC;
#pragma unroll
        for (int p = 0; p < 16; p++) {
            int id = tid + p * 256;       // 4096 chunks of 16B
            int row = id >> 5, ch = id & 31;
            cp_async16(xs + row * (PRW * 2) + ch * 16,
                       src + (size_t)row * NC + ch * 8);
        }
        CP_COMMIT();
    }
    // Load W fp32 -> bf16 smem: [128 o][256 c]
#pragma unroll
    for (int p = 0; p < 32; p++) {
        int id = tid + p * 256;           // 8192 float4
        int row = id >> 6, q = id & 63;
        float4 v = *(const float4*)(w + (size_t)row * NC + q * 4);
        uint32_t p0 = packbf(v.x, v.y), p1 = packbf(v.z, v.w);
        asm volatile("st.shared.v2.b32 [%0], {%1, %2};"
                     :: "r"(ws + row * (PRW * 2) + q * 8), "r"(p0), "r"(p1) : "memory");
    }
    CP_WAIT0();
    __syncthreads();

    // fragment addresses
    const int g = lane >> 3, row = lane & 7;
    const uint32_t abase = ws + (wm * 32 + (g & 1) * 8 + row) * (PRW * 2)
                              + ((g >> 1) * 8) * 2;
    const uint32_t bfo = ((g >> 1) * 8 + row) * (PRW * 2) + ((g & 1) * 8) * 2;

    float acc[2][8][4];
#pragma unroll
    for (int f = 0; f < 2; f++)
#pragma unroll
        for (int j = 0; j < 8; j++)
#pragma unroll
            for (int q = 0; q < 4; q++) acc[f][j][q] = 0.f;

#pragma unroll
    for (int ks = 0; ks < 16; ks++) {
        uint32_t a0[4], a1[4];
        ldmx4(abase + ks * 32, a0[0], a0[1], a0[2], a0[3]);
        ldmx4(abase + 16 * (PRW * 2) + ks * 32, a1[0], a1[1], a1[2], a1[3]);
#pragma unroll
        for (int nt = 0; nt < 4; nt++) {
            uint32_t b0, b1, b2, b3;
            ldmx4(xs + bfo + (wn * 64 + nt * 16) * (PRW * 2) + ks * 32, b0, b1, b2, b3);
            mma16816(acc[0][2 * nt],     a0, b0, b1);
            mma16816(acc[0][2 * nt + 1], a0, b2, b3);
            mma16816(acc[1][2 * nt],     a1, b0, b1);
            mma16816(acc[1][2 * nt + 1], a1, b2, b3);
        }
    }
    __syncthreads();

    // Stage C (+bias, *scale) into fp32 smem [o 128][n 128+4]
    float* es = (float*)dsm;
    const float sc = (mat == 0) ? QSCALE : 1.0f;
#pragma unroll
    for (int f = 0; f < 2; f++) {
        int mb = wm * 32 + f * 16 + (lane >> 2);
        float bv0 = (bias[mb] ) * sc + 0.f;   // scale applied to (acc+bias)
        float bv1 = (bias[mb + 8]) * sc;
#pragma unroll
        for (int j = 0; j < 8; j++) {
            int n = wn * 64 + j * 8 + (lane & 3) * 2;
            es[mb * 132 + n]           = acc[f][j][0] * sc + bv0;
            es[mb * 132 + n + 1]       = acc[f][j][1] * sc + bv0;
            es[(mb + 8) * 132 + n]     = acc[f][j][2] * sc + bv1;
            es[(mb + 8) * 132 + n + 1] = acc[f][j][3] * sc + bv1;
        }
    }
    __syncthreads();

    if (mat < 2) {
        // store [n][c]: 128 rows x 16 uint4
        __nv_bfloat16* dst = (mat == 0 ? g_Q : g_K) + (size_t)bb * NHW * NC2;
#pragma unroll
        for (int p = 0; p < 8; p++) {
            int id = tid + p * 256;
            int n = id >> 4, q = id & 15;
            uint32_t pk[4];
#pragma unroll
            for (int h = 0; h < 4; h++)
                pk[h] = packbf(es[(q * 8 + 2 * h) * 132 + n],
                               es[(q * 8 + 2 * h + 1) * 132 + n]);
            *(uint4*)(dst + (size_t)(n0 + n) * NC2 + q * 8) =
                make_uint4(pk[0], pk[1], pk[2], pk[3]);
        }
    } else {
        // store [c][n]: 128 rows x 16 uint4
        __nv_bfloat16* dst = g_V + (size_t)bb * NC2 * NHW;
#pragma unroll
        for (int p = 0; p < 8; p++) {
            int id = tid + p * 256;
            int r = id >> 4, q = id & 15;
            uint32_t pk[4];
#pragma unroll
            for (int h = 0; h < 4; h++)
                pk[h] = packbf(es[r * 132 + q * 8 + 2 * h],
                               es[r * 132 + q * 8 + 2 * h + 1]);
            *(uint4*)(dst + (size_t)r * NHW + n0 + q * 8) =
                make_uint4(pk[0], pk[1], pk[2], pk[3]);
        }
    }
}

// ---------------------------------------------------------------------------
// Kernel 2: bf16 mma.sync flash attention (no running max; fp32 row-sum).
// grid (64, 8), 128 threads (4 warps x 16 query rows). BC=64 keys per tile.
// Epilogue writes bf16 y [n][c].
// ---------------------------------------------------------------------------
#define KROW 136
#define VROW 72
#define QBYTES  (64 * KROW * 2)
#define KBYTES  (64 * KROW * 2)
#define VBYTES  (128 * VROW * 2)
#define ATTN_SMEM (QBYTES + 2 * KBYTES + 2 * VBYTES)   // 89088

__global__ __launch_bounds__(128, 2) void attn_kernel()
{
    extern __shared__ char dsm[];
    const uint32_t base = smem_u32(dsm);
    const uint32_t qsm = base;
    const uint32_t ksm[2] = { base + QBYTES, base + QBYTES + KBYTES };
    const uint32_t vsm[2] = { base + QBYTES + 2 * KBYTES,
                              base + QBYTES + 2 * KBYTES + VBYTES };

    const int tid  = threadIdx.x;
    const int warp = tid >> 5, lane = tid & 31;
    const int n0 = blockIdx.x * 64;
    const int bb = blockIdx.y;
    const __nv_bfloat16* Qg = g_Q + (size_t)bb * NHW * NC2;
    const __nv_bfloat16* Kg = g_K + (size_t)bb * NHW * NC2;
    const __nv_bfloat16* Vg = g_V + (size_t)bb * NC2 * NHW;

    const int qk_row = tid >> 4;
    const int qk_co  = (tid & 15) * 8;
    const int v_row  = tid >> 3;
    const int v_co   = (tid & 7) * 8;

#define LOAD_QK(dstbase, srcbase) do {                                        \
    const __nv_bfloat16* _s = (srcbase) + (size_t)qk_row * NC2 + qk_co;       \
    uint32_t _d = (dstbase) + qk_row * (KROW * 2) + qk_co * 2;                \
    _Pragma("unroll")                                                         \
    for (int p = 0; p < 8; p++)                                               \
        cp_async16(_d + p * 8 * (KROW * 2), _s + (size_t)p * 8 * NC2);        \
} while (0)

#define LOAD_V(dstbase, m0) do {                                              \
    const __nv_bfloat16* _s = Vg + (size_t)v_row * NHW + (m0) + v_co;         \
    uint32_t _d = (dstbase) + v_row * (VROW * 2) + v_co * 2;                  \
    _Pragma("unroll")                                                         \
    for (int p = 0; p < 8; p++)                                               \
        cp_async16(_d + p * 16 * (VROW * 2), _s + (size_t)p * 16 * NHW);      \
} while (0)

    LOAD_QK(qsm, Qg + (size_t)n0 * NC2);
    LOAD_QK(ksm[0], Kg);
    LOAD_V(vsm[0], 0);
    CP_COMMIT();
    LOAD_QK(ksm[1], Kg + (size_t)64 * NC2);
    LOAD_V(vsm[1], 64);
    CP_COMMIT();

    const int g   = lane >> 3;
    const int row = lane & 7;
    const uint32_t qbase = qsm + (warp * 16 + (g & 1) * 8 + row) * (KROW * 2)
                               + ((g >> 1) * 8) * 2;
    const uint32_t kfoff = ((g >> 1) * 8 + row) * (KROW * 2) + ((g & 1) * 8) * 2;
    const uint32_t vfoff = ((g >> 1) * 8 + row) * (VROW * 2) + ((g & 1) * 8) * 2;

    uint32_t qf[8][4];
    float o[16][4];
    float lsum0 = 0.f, lsum1 = 0.f;
#pragma unroll
    for (int i = 0; i < 16; i++)
#pragma unroll
        for (int j = 0; j < 4; j++) o[i][j] = 0.f;

    for (int kt = 0; kt < 64; kt++) {
        CP_WAIT1();
        __syncthreads();
        if (kt == 0) {
#pragma unroll
            for (int ks = 0; ks < 8; ks++)
                ldmx4(qbase + ks * 32, qf[ks][0], qf[ks][1], qf[ks][2], qf[ks][3]);
        }
        const uint32_t kb = ksm[kt & 1] + kfoff;
        const uint32_t vb = vsm[kt & 1] + vfoff;

        float s[8][4];
#pragma unroll
        for (int i = 0; i < 8; i++)
#pragma unroll
            for (int j = 0; j < 4; j++) s[i][j] = 0.f;
#pragma unroll
        for (int ks = 0; ks < 8; ks++) {
#pragma unroll
            for (int nt2 = 0; nt2 < 4; nt2++) {
                uint32_t b0, b1, b2, b3;
                ldmx4(kb + nt2 * 16 * (KROW * 2) + ks * 32, b0, b1, b2, b3);
                mma16816(s[2 * nt2],     qf[ks], b0, b1);
                mma16816(s[2 * nt2 + 1], qf[ks], b2, b3);
            }
        }

        uint32_t a[4][4];
#pragma unroll
        for (int nt = 0; nt < 8; nt++) {
            float e0 = fast_exp2(s[nt][0]);
            float e1 = fast_exp2(s[nt][1]);
            float e2 = fast_exp2(s[nt][2]);
            float e3 = fast_exp2(s[nt][3]);
            lsum0 += e0 + e1;
            lsum1 += e2 + e3;
            a[nt >> 1][(nt & 1) * 2]     = packbf(e0, e1);
            a[nt >> 1][(nt & 1) * 2 + 1] = packbf(e2, e3);
        }

#pragma unroll
        for (int ks = 0; ks < 4; ks++) {
#pragma unroll
            for (int ct2 = 0; ct2 < 8; ct2++) {
                uint32_t b0, b1, b2, b3;
                ldmx4(vb + ct2 * 16 * (VROW * 2) + ks * 32, b0, b1, b2, b3);
                mma16816(o[2 * ct2],     a[ks], b0, b1);
                mma16816(o[2 * ct2 + 1], a[ks], b2, b3);
            }
        }

        __syncthreads();
        if (kt + 2 < 64) {
            LOAD_QK(ksm[kt & 1], Kg + (size_t)(kt + 2) * 64 * NC2);
            LOAD_V(vsm[kt & 1], (kt + 2) * 64);
        }
        CP_COMMIT();
    }

    CP_WAIT0();
    __syncthreads();

    lsum0 += __shfl_xor_sync(0xffffffffu, lsum0, 1);
    lsum0 += __shfl_xor_sync(0xffffffffu, lsum0, 2);
    lsum1 += __shfl_xor_sync(0xffffffffu, lsum1, 1);
    lsum1 += __shfl_xor_sync(0xffffffffu, lsum1, 2);
    const float inv0 = 1.0f / lsum0;
    const float inv1 = 1.0f / lsum1;

    // stage O into smem [c:128][q:64+4 pad] fp32
    float* es = (float*)dsm;
    const int m_lo = warp * 16 + (lane >> 2);
#pragma unroll
    for (int nt = 0; nt < 16; nt++) {
        int c = nt * 8 + (lane & 3) * 2;
        es[(c)     * 68 + m_lo]     = o[nt][0] * inv0;
        es[(c + 1) * 68 + m_lo]     = o[nt][1] * inv0;
        es[(c)     * 68 + m_lo + 8] = o[nt][2] * inv1;
        es[(c + 1) * 68 + m_lo + 8] = o[nt][3] * inv1;
    }
    __syncthreads();

    // write y bf16 [n][c]
    __nv_bfloat16* yb = g_Yb + (size_t)bb * NHW * NC2;
#pragma unroll
    for (int p = 0; p < 8; p++) {
        int id = tid + p * 128;           // 1024 uint4 chunks
        int n = id >> 4, q = id & 15;
        uint32_t pk[4];
#pragma unroll
        for (int h = 0; h < 4; h++)
            pk[h] = packbf(es[(q * 8 + 2 * h) * 68 + n],
                           es[(q * 8 + 2 * h + 1) * 68 + n]);
        *(uint4*)(yb + (size_t)(n0 + n) * NC2 + q * 8) =
            make_uint4(pk[0], pk[1], pk[2], pk[3]);
    }
}

// ---------------------------------------------------------------------------
// Kernel 3: out conv (bf16 mma) + BN(eval) + residual.
// grid (32, 8), 256 thr (8 warps, warpM=32, warpN=128).
// C[o 256][n 128] = sum_c Wout[o][c] * Y[n][c], K=128.
// smem: Ws bf16[256][136] | Ys bf16[128][136]
// ---------------------------------------------------------------------------
#define ORW 136
#define OUT_SMEM (256 * ORW * 2 + 128 * ORW * 2)   // 104448

__global__ __launch_bounds__(256) void out_mma(
    const float* __restrict__ x,
    const float* __restrict__ w_out, const float* __restrict__ b_out,
    const float* __restrict__ gamma, const float* __restrict__ beta,
    const float* __restrict__ rmean, const float* __restrict__ rvar,
    float* __restrict__ out)
{
    extern __shared__ char dsm[];
    const uint32_t ws = smem_u32(dsm);
    const uint32_t ys = ws + 256 * ORW * 2;

    const int n0 = blockIdx.x * 128;
    const int bb = blockIdx.y;
    const int tid  = threadIdx.x;
    const int warp = tid >> 5, lane = tid & 31;

    // Load Y tile via cp.async: [128 n][128 c] bf16
    {
        const __nv_bfloat16* src = g_Yb + (size_t)bb * NHW * NC2 + (size_t)n0 * NC2;
#pragma unroll
        for (int p = 0; p < 8; p++) {
            int id = tid + p * 256;       // 2048 chunks
            int row = id >> 4, ch = id & 15;
            cp_async16(ys + row * (ORW * 2) + ch * 16,
                       src + (size_t)row * NC2 + ch * 8);
        }
        CP_COMMIT();
    }
    // Load Wout fp32 [256][128] -> bf16 smem
#pragma unroll
    for (int p = 0; p < 32; p++) {
        int id = tid + p * 256;           // 8192 float4
        int row = id >> 5, q = id & 31;
        float4 v = *(const float4*)(w_out + (size_t)row * NC2 + q * 4);
        uint32_t p0 = packbf(v.x, v.y), p1 = packbf(v.z, v.w);
        asm volatile("st.shared.v2.b32 [%0], {%1, %2};"
                     :: "r"(ws + row * (ORW * 2) + q * 8), "r"(p0), "r"(p1) : "memory");
    }
    CP_WAIT0();
    __syncthreads();

    const int g = lane >> 3, row = lane & 7;
    const uint32_t abase = ws + (warp * 32 + (g & 1) * 8 + row) * (ORW * 2)
                              + ((g >> 1) * 8) * 2;
    const uint32_t bfo = ((g >> 1) * 8 + row) * (ORW * 2) + ((g & 1) * 8) * 2;

    float acc[2][16][4];
#pragma unroll
    for (int f = 0; f < 2; f++)
#pragma unroll
        for (int j = 0; j < 16; j++)
#pragma unroll
            for (int q = 0; q < 4; q++) acc[f][j][q] = 0.f;

#pragma unroll
    for (int ks = 0; ks < 8; ks++) {
        uint32_t a0[4], a1[4];
        ldmx4(abase + ks * 32, a0[0], a0[1], a0[2], a0[3]);
        ldmx4(abase + 16 * (ORW * 2) + ks * 32, a1[0], a1[1], a1[2], a1[3]);
#pragma unroll
        for (int nt = 0; nt < 8; nt++) {
            uint32_t b0, b1, b2, b3;
            ldmx4(ys + bfo + nt * 16 * (ORW * 2) + ks * 32, b0, b1, b2, b3);
            mma16816(acc[0][2 * nt],     a0, b0, b1);
            mma16816(acc[0][2 * nt + 1], a0, b2, b3);
            mma16816(acc[1][2 * nt],     a1, b0, b1);
            mma16816(acc[1][2 * nt + 1], a1, b2, b3);
        }
    }

    // BN + residual epilogue (direct stores; 4 owned o-rows per f-half)
    const float* xb = x + (size_t)bb * NC * NHW;
    float* ob = out + (size_t)bb * NC * NHW;
#pragma unroll
    for (int f = 0; f < 2; f++) {
        const int m0 = warp * 32 + f * 16 + (lane >> 2);
        const int m1 = m0 + 8;
        float iv0 = gamma[m0] * rsqrtf(rvar[m0] + 1e-5f);
        float iv1 = gamma[m1] * rsqrtf(rvar[m1] + 1e-5f);
        float sh0 = beta[m0] - rmean[m0] * iv0 + b_out[m0] * iv0;
        float sh1 = beta[m1] - rmean[m1] * iv1 + b_out[m1] * iv1;
#pragma unroll
        for (int j = 0; j < 16; j++) {
            int n = n0 + j * 8 + (lane & 3) * 2;
            float2 x0 = *(const float2*)(xb + (size_t)m0 * NHW + n);
            float2 x1 = *(const float2*)(xb + (size_t)m1 * NHW + n);
            float2 v0, v1;
            v0.x = x0.x + acc[f][j][0] * iv0 + sh0;
            v0.y = x0.y + acc[f][j][1] * iv0 + sh0;
            v1.x = x1.x + acc[f][j][2] * iv1 + sh1;
            v1.y = x1.y + acc[f][j][3] * iv1 + sh1;
            *(float2*)(ob + (size_t)m0 * NHW + n) = v0;
            *(float2*)(ob + (size_t)m1 * NHW + n) = v1;
        }
    }
}

// ---------------------------------------------------------------------------
extern "C" void kernel_launch(void* const* d_in, const int* in_sizes, int n_in,
                              void* d_out, int out_size)
{
    const float* x       = (const float*)d_in[0];
    const float* w_theta = (const float*)d_in[1];
    const float* b_theta = (const float*)d_in[2];
    const float* w_phi   = (const float*)d_in[3];
    const float* b_phi   = (const float*)d_in[4];
    const float* w_g     = (const float*)d_in[5];
    const float* b_g     = (const float*)d_in[6];
    const float* w_out   = (const float*)d_in[7];
    const float* b_out   = (const float*)d_in[8];
    const float* gamma   = (const float*)d_in[9];
    const float* beta    = (const float*)d_in[10];
    const float* rmean   = (const float*)d_in[11];
    const float* rvar    = (const float*)d_in[12];
    float* out = (float*)d_out;

    cudaFuncSetAttribute(attn_kernel,
                         cudaFuncAttributeMaxDynamicSharedMemorySize, ATTN_SMEM);
    cudaFuncSetAttribute(proj_mma,
                         cudaFuncAttributeMaxDynamicSharedMemorySize, PROJ_SMEM);
    cudaFuncSetAttribute(out_mma,
                         cudaFuncAttributeMaxDynamicSharedMemorySize, OUT_SMEM);

    dim3 g0(NHW / 64, NC / 64, NB);
    convert_kernel<<<g0, 128>>>(x);

    dim3 g1(NHW / 128, 3, NB);
    proj_mma<<<g1, 256, PROJ_SMEM>>>(w_theta, b_theta, w_phi, b_phi, w_g, b_g);

    dim3 g2(NHW / 64, NB);
    attn_kernel<<<g2, 128, ATTN_SMEM>>>();

    dim3 g3(NHW / 128, NB);
    out_mma<<<g3, 256, OUT_SMEM>>>(x, w_out, b_out, gamma, beta, rmean, rvar, out);
}